// round 2
// baseline (speedup 1.0000x reference)
#include <cuda_runtime.h>
#include <math.h>

#define BB 64
#define TT 512
#define II 256
#define HH 512
#define CC 40
#define G4 2048     // 4*H
#define NB 128      // persistent blocks (must be <= #SMs, all co-resident)
#define WPAD 516    // padded row stride for W slice in smem

// -------------------- device scratch (no allocations allowed) --------------------
__device__ float g_xg [(size_t)BB * TT * G4];   // [m=b*T+t][n]   256 MB
__device__ float g_xgT[(size_t)TT * G4 * BB];   // [t][n][b]      256 MB
__device__ float g_hbuf[2 * HH * BB];           // [parity][unit][b]  k-major h
__device__ unsigned g_arrive;                   // zero-init at module load
__device__ unsigned g_gen;

// -------------------- helpers --------------------
__device__ __forceinline__ float fsig(float x) { return 1.f / (1.f + __expf(-x)); }
__device__ __forceinline__ float ftanh(float x) {
    float ax = fabsf(x);
    float e  = __expf(-2.f * ax);
    float r  = (1.f - e) / (1.f + e);
    return x < 0.f ? -r : r;
}

__device__ __forceinline__ void gridbar() {
    __syncthreads();
    if (threadIdx.x == 0) {
        unsigned gen = *((volatile unsigned*)&g_gen);
        __threadfence();
        unsigned t = atomicAdd(&g_arrive, 1u);
        if (t == NB - 1) {
            *((volatile unsigned*)&g_arrive) = 0u;
            __threadfence();
            atomicAdd(&g_gen, 1u);
        } else {
            while (*((volatile unsigned*)&g_gen) == gen) { }
            __threadfence();
        }
    }
    __syncthreads();
}

// -------------------- kernel 1: xg = x @ W_ih^T + (b_ih + b_hh) --------------------
// C[m][n], m in 32768, n in 2048, k in 256.  128x128 tile, 8x8 per thread.
__global__ void __launch_bounds__(256) gemm_xg(const float* __restrict__ x,
                                               const float* __restrict__ Wih,
                                               const float* __restrict__ bih,
                                               const float* __restrict__ bhh) {
    __shared__ float As[16][132];   // [k][m]
    __shared__ float Bs[16][132];   // [k][n]
    const int tid  = threadIdx.x;
    const int m0   = blockIdx.y * 128;
    const int n0   = blockIdx.x * 128;
    const int tx   = tid & 15;      // n micro-tile
    const int ty   = tid >> 4;      // m micro-tile
    const int lrow = tid >> 2;      // 0..63
    const int lkq  = (tid & 3) << 2;// 0,4,8,12

    float acc[8][8];
#pragma unroll
    for (int i = 0; i < 8; i++)
#pragma unroll
        for (int j = 0; j < 8; j++) acc[i][j] = 0.f;

    for (int k0 = 0; k0 < II; k0 += 16) {
        float4 a0 = *(const float4*)(x   + (size_t)(m0 + lrow)      * II + k0 + lkq);
        float4 a1 = *(const float4*)(x   + (size_t)(m0 + lrow + 64) * II + k0 + lkq);
        float4 b0 = *(const float4*)(Wih + (size_t)(n0 + lrow)      * II + k0 + lkq);
        float4 b1 = *(const float4*)(Wih + (size_t)(n0 + lrow + 64) * II + k0 + lkq);
        __syncthreads();
        As[lkq+0][lrow]    = a0.x; As[lkq+1][lrow]    = a0.y;
        As[lkq+2][lrow]    = a0.z; As[lkq+3][lrow]    = a0.w;
        As[lkq+0][lrow+64] = a1.x; As[lkq+1][lrow+64] = a1.y;
        As[lkq+2][lrow+64] = a1.z; As[lkq+3][lrow+64] = a1.w;
        Bs[lkq+0][lrow]    = b0.x; Bs[lkq+1][lrow]    = b0.y;
        Bs[lkq+2][lrow]    = b0.z; Bs[lkq+3][lrow]    = b0.w;
        Bs[lkq+0][lrow+64] = b1.x; Bs[lkq+1][lrow+64] = b1.y;
        Bs[lkq+2][lrow+64] = b1.z; Bs[lkq+3][lrow+64] = b1.w;
        __syncthreads();
#pragma unroll
        for (int k = 0; k < 16; k++) {
            float a[8], bvals[8];
            *(float4*)(a)         = *(float4*)&As[k][ty * 8];
            *(float4*)(a + 4)     = *(float4*)&As[k][ty * 8 + 4];
            *(float4*)(bvals)     = *(float4*)&Bs[k][tx * 8];
            *(float4*)(bvals + 4) = *(float4*)&Bs[k][tx * 8 + 4];
#pragma unroll
            for (int i = 0; i < 8; i++)
#pragma unroll
                for (int j = 0; j < 8; j++)
                    acc[i][j] = fmaf(a[i], bvals[j], acc[i][j]);
        }
    }

    float bias[8];
#pragma unroll
    for (int j = 0; j < 8; j++) {
        int n = n0 + tx * 8 + j;
        bias[j] = bih[n] + bhh[n];
    }
#pragma unroll
    for (int i = 0; i < 8; i++) {
        size_t m = (size_t)(m0 + ty * 8 + i);
        float4 v0, v1;
        v0.x = acc[i][0] + bias[0]; v0.y = acc[i][1] + bias[1];
        v0.z = acc[i][2] + bias[2]; v0.w = acc[i][3] + bias[3];
        v1.x = acc[i][4] + bias[4]; v1.y = acc[i][5] + bias[5];
        v1.z = acc[i][6] + bias[6]; v1.w = acc[i][7] + bias[7];
        *(float4*)(g_xg + m * G4 + n0 + tx * 8)     = v0;
        *(float4*)(g_xg + m * G4 + n0 + tx * 8 + 4) = v1;
    }
}

// -------------------- kernel 2: transpose xg[b*T+t][n] -> xgT[t][n][b] --------------------
__global__ void __launch_bounds__(256) transpose_xg() {
    __shared__ float tile[64][65];
    const int t   = blockIdx.x;
    const int n0  = blockIdx.y << 6;
    const int tid = threadIdx.x;
    const int a   = tid & 63;   // inner index (n on read, b on write)
    const int r   = tid >> 6;   // 0..3
    for (int b = r; b < 64; b += 4)
        tile[a][b] = g_xg[(size_t)(b * TT + t) * G4 + n0 + a];
    __syncthreads();
    for (int n = r; n < 64; n += 4)
        g_xgT[((size_t)t * G4 + n0 + n) * BB + a] = tile[n][a];
}

// -------------------- kernel 3: persistent LSTM recurrence --------------------
// 128 blocks x 256 threads. Block bx owns hidden units [4*bx, 4*bx+4) -> 16 gate rows.
// smem: hsT (h staged k-major, 128KB) | Wsm (16 x 516, 33KB) | red (4x16x64, 16KB)
__global__ void __launch_bounds__(256, 1) lstm_rec(const float* __restrict__ Whh) {
    extern __shared__ float sm[];
    float4* hsT4 = (float4*)sm;               // [512*16] float4 == h[k][b]
    float*  Wsm  = sm + HH * 64;              // [16][WPAD]
    float*  red  = Wsm + 16 * WPAD;           // [4][16][64]

    const int tid = threadIdx.x;
    const int bx  = blockIdx.x;

    // Load W_hh slice: local row lr = g*4 + uu  -> global row g*512 + bx*4 + uu
    for (int idx = tid; idx < 16 * 512; idx += 256) {
        int lr  = idx >> 9;
        int k   = idx & 511;
        int row = ((lr >> 2) << 9) + (bx << 2) + (lr & 3);
        Wsm[lr * WPAD + k] = Whh[(size_t)row * HH + k];
    }

    // elementwise-role mapping
    const int b  = tid & 63;
    const int uu = tid >> 6;           // 0..3
    const int ug = (bx << 2) + uu;     // global unit

    g_hbuf[ug * 64 + b] = 0.f;         // h0 = 0 (parity 0)
    float c = 0.f;                     // cell state lives in a register
    __threadfence();
    gridbar();

    // compute-role mapping: split-k x4, 2 rows x 8 batches per thread
    const int kg = tid >> 6;           // 0..3   -> k in [kg*128, kg*128+128)
    const int rq = (tid >> 3) & 7;     // 0..7   -> rows rq*2, rq*2+1
    const int bq = tid & 7;            // 0..7   -> batches bq*8..bq*8+7
    const int k0 = kg << 7;
    const float* w0p = Wsm + (rq * 2) * WPAD;
    const float* w1p = w0p + WPAD;
    const float4* hb4 = (const float4*)g_hbuf;
    float4* red4 = (float4*)red;
    const int rbase = ((kg << 4) + (rq << 1)) * 16 + (bq << 1);

    for (int t = 0; t < TT; t++) {
        const int p = t & 1;
        // stage h (L2-fresh: other SMs wrote it; bypass incoherent L1)
        const float4* src = hb4 + p * (HH * 16);
#pragma unroll
        for (int i = 0; i < 32; i++)
            hsT4[tid + i * 256] = __ldcg(src + tid + i * 256);
        __syncthreads();

        float acc0[8], acc1[8];
#pragma unroll
        for (int j = 0; j < 8; j++) { acc0[j] = 0.f; acc1[j] = 0.f; }

#pragma unroll 4
        for (int k = k0; k < k0 + 128; k++) {
            float4 h0 = hsT4[(k << 4) + (bq << 1)];
            float4 h1 = hsT4[(k << 4) + (bq << 1) + 1];
            float w0 = w0p[k];
            float w1 = w1p[k];
            acc0[0] = fmaf(w0, h0.x, acc0[0]);
            acc0[1] = fmaf(w0, h0.y, acc0[1]);
            acc0[2] = fmaf(w0, h0.z, acc0[2]);
            acc0[3] = fmaf(w0, h0.w, acc0[3]);
            acc0[4] = fmaf(w0, h1.x, acc0[4]);
            acc0[5] = fmaf(w0, h1.y, acc0[5]);
            acc0[6] = fmaf(w0, h1.z, acc0[6]);
            acc0[7] = fmaf(w0, h1.w, acc0[7]);
            acc1[0] = fmaf(w1, h0.x, acc1[0]);
            acc1[1] = fmaf(w1, h0.y, acc1[1]);
            acc1[2] = fmaf(w1, h0.z, acc1[2]);
            acc1[3] = fmaf(w1, h0.w, acc1[3]);
            acc1[4] = fmaf(w1, h1.x, acc1[4]);
            acc1[5] = fmaf(w1, h1.y, acc1[5]);
            acc1[6] = fmaf(w1, h1.z, acc1[6]);
            acc1[7] = fmaf(w1, h1.w, acc1[7]);
        }

        red4[rbase]      = make_float4(acc0[0], acc0[1], acc0[2], acc0[3]);
        red4[rbase + 1]  = make_float4(acc0[4], acc0[5], acc0[6], acc0[7]);
        red4[rbase + 16] = make_float4(acc1[0], acc1[1], acc1[2], acc1[3]);
        red4[rbase + 17] = make_float4(acc1[4], acc1[5], acc1[6], acc1[7]);
        __syncthreads();

        // elementwise: combine split-k partials + xg, gate nonlinearity, state update
        float s[4];
#pragma unroll
        for (int g = 0; g < 4; g++) {
            int lr = (g << 2) + uu;
            float v = red[lr * 64 + b] + red[(16 + lr) * 64 + b]
                    + red[(32 + lr) * 64 + b] + red[(48 + lr) * 64 + b];
            s[g] = v + g_xgT[((size_t)t * G4 + (g << 9) + ug) * 64 + b];
        }
        float ig = fsig(s[0]);
        float fg = fsig(s[1]);
        float gg = ftanh(s[2]);
        float og = fsig(s[3]);
        c = fmaf(fg, c, ig * gg);
        float h = og * ftanh(c);
        g_hbuf[((p ^ 1) * HH + ug) * 64 + b] = h;
        __threadfence();
        gridbar();
    }
    // after t=511 (odd), h_last sits in parity 0: g_hbuf[0 .. HH*BB)
}

// -------------------- kernel 4: out = h_last @ W_fc^T + b_fc --------------------
__global__ void __launch_bounds__(256) fc_out(const float* __restrict__ Wfc,
                                              const float* __restrict__ bfc,
                                              float* __restrict__ out) {
    __shared__ float hs[HH];
    const int b = blockIdx.x;
    for (int u = threadIdx.x; u < HH; u += 256) hs[u] = g_hbuf[u * 64 + b];
    __syncthreads();
    const int w = threadIdx.x >> 5, lane = threadIdx.x & 31;
    for (int cc = w; cc < CC; cc += 8) {
        float s = 0.f;
        for (int u = lane; u < HH; u += 32) s = fmaf(hs[u], Wfc[cc * HH + u], s);
#pragma unroll
        for (int o = 16; o; o >>= 1) s += __shfl_xor_sync(0xffffffffu, s, o);
        if (lane == 0) out[b * CC + cc] = s + bfc[cc];
    }
}

// -------------------- launch --------------------
extern "C" void kernel_launch(void* const* d_in, const int* in_sizes, int n_in,
                              void* d_out, int out_size) {
    (void)in_sizes; (void)n_in; (void)out_size;
    const float* x   = (const float*)d_in[0];
    const float* Wih = (const float*)d_in[1];
    const float* Whh = (const float*)d_in[2];
    const float* bih = (const float*)d_in[3];
    const float* bhh = (const float*)d_in[4];
    const float* Wfc = (const float*)d_in[5];
    const float* bfc = (const float*)d_in[6];
    float* out = (float*)d_out;

    gemm_xg<<<dim3(G4 / 128, (BB * TT) / 128), 256>>>(x, Wih, bih, bhh);
    transpose_xg<<<dim3(TT, G4 / 64), 256>>>();

    constexpr size_t SMEM = (size_t)(HH * 64 + 16 * WPAD + 4 * 16 * 64) * sizeof(float);
    cudaFuncSetAttribute(lstm_rec, cudaFuncAttributeMaxDynamicSharedMemorySize, (int)SMEM);
    lstm_rec<<<NB, 256, SMEM>>>(Whh);

    fc_out<<<BB, 256>>>(Wfc, bfc, out);
}